// round 16
// baseline (speedup 1.0000x reference)
#include <cuda_runtime.h>
#include <cuda_fp16.h>
#include <cstdint>

#define N_NODES 50000
#define N_EDGES 625000
#define F 128
#define SCAN_BLOCKS 49          // 49 * 1024 = 50176 >= N_NODES
#define TILE_M 128
#define GEMM_BLOCKS ((N_NODES + TILE_M - 1) / TILE_M)   // 391
#define GEMM_THREADS 512
#define SPAD 136                // padded row stride (fp16 elems) -> conflict-free LDSM
#define TILE_BYTES (128 * SPAD * 2)                     // 34816
#define GEMM_SMEM (2 * TILE_BYTES)                      // A + B = 69632 -> 2 CTAs/SM
#define AGG_FLAG (1 << 30)
#define SCAT_ILP 4
#define SCAT_NT ((N_EDGES + SCAT_ILP - 1) / SCAT_ILP)   // 156250 threads

// ---------------------------------------------------------------------------
// Scratch (__device__ globals => allocation-free)
// Invariant: g_count[] == 0 at entry of every kernel_launch call
// (zero-init at load; scatter's atomicSub cursor restores it each call).
// ---------------------------------------------------------------------------
__device__ __half g_support[(size_t)N_NODES * F]; // x @ W, fp16 (12.8 MB)
__device__ int    g_count[N_NODES];               // histogram / cursor
__device__ int    g_start[N_NODES + 1];           // CSR row starts
__device__ int2   g_edge[N_EDGES];                // packed {col, val} by row
__device__ int    g_agg[SCAN_BLOCKS];             // lookback aggregates
__device__ __half g_wt[F * F];                    // W^T (fp16), [n][k]

__device__ __forceinline__ uint32_t smem_u32(const void* p) {
    uint32_t a;
    asm("{ .reg .u64 t; cvta.to.shared.u64 t, %1; cvt.u32.u64 %0, t; }" : "=r"(a) : "l"(p));
    return a;
}

#define LDSM4(r0, r1, r2, r3, addr)                                              \
    asm volatile("ldmatrix.sync.aligned.m8n8.x4.shared.b16 {%0,%1,%2,%3}, [%4];" \
                 : "=r"(r0), "=r"(r1), "=r"(r2), "=r"(r3) : "r"(addr))

#define MMA16816F16(c, a0, a1, a2, a3, b0, b1)                                   \
    asm volatile("mma.sync.aligned.m16n8k16.row.col.f32.f16.f16.f32 "            \
                 "{%0,%1,%2,%3}, {%4,%5,%6,%7}, {%8,%9}, {%0,%1,%2,%3};"         \
                 : "+f"((c)[0]), "+f"((c)[1]), "+f"((c)[2]), "+f"((c)[3])        \
                 : "r"(a0), "r"(a1), "r"(a2), "r"(a3), "r"(b0), "r"(b1))

// ---------------------------------------------------------------------------
// Kernel 1: GEMM (single-term fp16 HMMA, 128x128 tile, 2 CTAs/SM)
//           + fused edge histogram + lookback-flag reset
// 512 threads; warp w: rows [16*(w>>1), +16), cols [64*(w&1), +64).
// ---------------------------------------------------------------------------
__global__ __launch_bounds__(GEMM_THREADS, 2)
void gemm_hist_kernel(const float* __restrict__ x, const int* __restrict__ rows) {
    extern __shared__ char smem[];
    __half* sA = (__half*)smem;                  // 128 x SPAD fp16
    __half* sB = sA + 128 * SPAD;                // 128 x SPAD fp16 (W^T)

    const int t   = threadIdx.x;
    const int m0  = blockIdx.x * TILE_M;
    const int gid = blockIdx.x * GEMM_THREADS + t;

    // ---- Fused: edge-row histogram (overlaps the tile-load latency) ----
    for (int e = gid; e < N_EDGES; e += GEMM_BLOCKS * GEMM_THREADS)
        atomicAdd(&g_count[rows[e]], 1);
    if (gid < SCAN_BLOCKS) g_agg[gid] = 0;

    // ---- Load x tile, convert to fp16, padded stride ----
    #pragma unroll 4
    for (int i = 0; i < 8; i++) {
        int idx = t + GEMM_THREADS * i;          // 4096 float4 slots (128 x 32)
        int row = idx >> 5;
        int c4  = (idx & 31) * 4;
        int m   = m0 + row;
        float4 xv = (m < N_NODES) ? ((const float4*)x)[((size_t)m * F + c4) >> 2]
                                  : make_float4(0.f, 0.f, 0.f, 0.f);
        __half2 p0 = __floats2half2_rn(xv.x, xv.y);
        __half2 p1 = __floats2half2_rn(xv.z, xv.w);
        *(__half2*)&sA[row * SPAD + c4]     = p0;
        *(__half2*)&sA[row * SPAD + c4 + 2] = p1;
    }

    // ---- Copy pre-converted W^T (fp16) into smem, padded stride ----
    // 128 rows x 16 uint4 slots = 2048 slots; 512 threads -> 4 iterations.
    #pragma unroll
    for (int i = 0; i < 4; i++) {
        int idx = t + GEMM_THREADS * i;
        int n   = idx >> 4;
        int c8  = (idx & 15) * 8;
        *(uint4*)&sB[n * SPAD + c8] = *(const uint4*)&g_wt[n * F + c8];
    }
    __syncthreads();

    const int wid  = t >> 5;
    const int lane = t & 31;
    const int R    = (wid >> 1) * 16;            // row base (0..112)
    const int C0   = (wid & 1) * 64;             // col base

    float acc[8][4];
    #pragma unroll
    for (int i = 0; i < 8; i++)
        #pragma unroll
        for (int j = 0; j < 4; j++) acc[i][j] = 0.f;

    const uint32_t aBase = smem_u32(smem);
    const uint32_t bBase = aBase + TILE_BYTES;

    const int arow    = R + (lane & 7) + ((lane >> 3) & 1) * 8;
    const int acolh   = (lane >> 4) * 8;
    const int brow_in = (lane & 7) + ((lane >= 16) ? 8 : 0);
    const int bcolh   = ((lane >> 3) & 1) * 8;

    #pragma unroll 1
    for (int kc = 0; kc < 8; kc++) {
        const int k0 = kc * 16;
        uint32_t a0, a1, a2, a3;
        LDSM4(a0, a1, a2, a3, aBase + (uint32_t)((arow * SPAD + k0 + acolh) * 2));

        #pragma unroll
        for (int np = 0; np < 4; np++) {
            const int ncol = C0 + np * 16;
            uint32_t b0, b1, b2, b3;
            LDSM4(b0, b1, b2, b3,
                  bBase + (uint32_t)(((ncol + brow_in) * SPAD + k0 + bcolh) * 2));
            MMA16816F16(acc[2 * np],     a0, a1, a2, a3, b0, b1);
            MMA16816F16(acc[2 * np + 1], a0, a1, a2, a3, b2, b3);
        }
    }

    // ---- Epilogue: accum regs -> g_support as fp16 (half2 per 2 cols) ----
    const int g   = lane >> 2;
    const int tig = lane & 3;
    const int m1  = m0 + R + g;
    const int m2  = m1 + 8;
    #pragma unroll
    for (int nt = 0; nt < 8; nt++) {
        const int c = C0 + nt * 8 + tig * 2;
        if (m1 < N_NODES)
            *(__half2*)&g_support[(size_t)m1 * F + c] = __floats2half2_rn(acc[nt][0], acc[nt][1]);
        if (m2 < N_NODES)
            *(__half2*)&g_support[(size_t)m2 * F + c] = __floats2half2_rn(acc[nt][2], acc[nt][3]);
    }
}

// ---------------------------------------------------------------------------
// Kernel 0: W^T fp16 convert (tiny)
// ---------------------------------------------------------------------------
__global__ void prep_w_kernel(const float* __restrict__ w) {
    int i = blockIdx.x * blockDim.x + threadIdx.x;   // i = n*F + k
    if (i >= F * F) return;
    int n = i >> 7, k = i & 127;
    g_wt[i] = __float2half(w[k * F + n]);
}

// ---------------------------------------------------------------------------
// Kernel 2: single-pass exclusive scan of g_count -> g_start
// 49 co-resident blocks; decoupled lookback, full-predecessor stride.
// ---------------------------------------------------------------------------
__global__ __launch_bounds__(1024) void scan_fused_kernel() {
    __shared__ int wsum[32];
    __shared__ int blk_prev;
    const int t    = threadIdx.x;
    const int bid  = blockIdx.x;
    const int lane = t & 31;
    const int wid  = t >> 5;
    const int idx  = bid * 1024 + t;

    const int v = (idx < N_NODES) ? g_count[idx] : 0;

    int s = v;
    #pragma unroll
    for (int off = 1; off < 32; off <<= 1) {
        int n = __shfl_up_sync(0xffffffffu, s, off);
        if (lane >= off) s += n;
    }
    if (lane == 31) wsum[wid] = s;
    __syncthreads();

    if (wid == 0) {
        int ws = wsum[lane];
        #pragma unroll
        for (int off = 1; off < 32; off <<= 1) {
            int n = __shfl_up_sync(0xffffffffu, ws, off);
            if (lane >= off) ws += n;
        }
        wsum[lane] = ws;
        if (lane == 31) atomicExch(&g_agg[bid], ws | AGG_FLAG);

        int a = 0;
        for (int p = lane; p < bid; p += 32) {
            volatile int* agg = g_agg;
            int xv;
            do { xv = agg[p]; } while (!(xv & AGG_FLAG));
            a += xv & (AGG_FLAG - 1);
        }
        #pragma unroll
        for (int off = 16; off >= 1; off >>= 1)
            a += __shfl_xor_sync(0xffffffffu, a, off);
        if (lane == 0) blk_prev = a;
    }
    __syncthreads();

    const int wexcl = (wid > 0) ? wsum[wid - 1] : 0;
    if (idx < N_NODES) g_start[idx] = blk_prev + wexcl + (s - v);
    if (idx == 0) g_start[N_NODES] = N_EDGES;
}

// ---------------------------------------------------------------------------
// Kernel 3: scatter edges into CSR order — MLP-4.
// Each thread owns 4 edges at stride SCAT_NT (coalesced); the 4 chains
// (load -> atomicSub -> store) are independent -> 4 in flight.
// atomicSub cursor returns g_count to all-zero (invariant).
// ---------------------------------------------------------------------------
__global__ __launch_bounds__(256) void scatter_kernel(const int*   __restrict__ rows,
                                                      const int*   __restrict__ cols,
                                                      const float* __restrict__ vals) {
    const int tid = blockIdx.x * blockDim.x + threadIdx.x;
    if (tid >= SCAT_NT) return;

    int   r[SCAT_ILP], c[SCAT_ILP];
    float v[SCAT_ILP];
    bool  ok[SCAT_ILP];

    #pragma unroll
    for (int k = 0; k < SCAT_ILP; k++) {
        int e = tid + k * SCAT_NT;
        ok[k] = (e < N_EDGES);
        r[k] = ok[k] ? rows[e] : 0;
        c[k] = ok[k] ? cols[e] : 0;
        v[k] = ok[k] ? vals[e] : 0.f;
    }

    int p[SCAT_ILP];
    #pragma unroll
    for (int k = 0; k < SCAT_ILP; k++)
        p[k] = ok[k] ? (g_start[r[k]] + atomicSub(&g_count[r[k]], 1) - 1) : 0;

    #pragma unroll
    for (int k = 0; k < SCAT_ILP; k++)
        if (ok[k]) g_edge[p[k]] = make_int2(c[k], __float_as_int(v[k]));
}

// ---------------------------------------------------------------------------
// Kernel 4: CSR SpMM: warp per row, 4-edge ILP, fp16 gathers (uint2/lane),
// fp32 accumulation, bias fused, atomic-free.
// ---------------------------------------------------------------------------
__device__ __forceinline__ void fma_half4(float4& acc, float v, uint2 u) {
    const float2 f0 = __half22float2(*reinterpret_cast<__half2*>(&u.x));
    const float2 f1 = __half22float2(*reinterpret_cast<__half2*>(&u.y));
    acc.x += v * f0.x; acc.y += v * f0.y;
    acc.z += v * f1.x; acc.w += v * f1.y;
}

__global__ __launch_bounds__(256) void spmm_csr_kernel(const float* __restrict__ bias,
                                                       float*       __restrict__ out) {
    const int warp = (blockIdx.x * blockDim.x + threadIdx.x) >> 5;
    const int lane = threadIdx.x & 31;
    if (warp >= N_NODES) return;

    const int s = g_start[warp];
    const int e = g_start[warp + 1];

    float4 acc = ((const float4*)bias)[lane];

    int base = s;
    for (; base + 4 <= e; base += 4) {
        const int2 e0 = g_edge[base + 0];
        const int2 e1 = g_edge[base + 1];
        const int2 e2 = g_edge[base + 2];
        const int2 e3 = g_edge[base + 3];
        const uint2 u0 = *(const uint2*)&g_support[(size_t)e0.x * F + lane * 4];
        const uint2 u1 = *(const uint2*)&g_support[(size_t)e1.x * F + lane * 4];
        const uint2 u2 = *(const uint2*)&g_support[(size_t)e2.x * F + lane * 4];
        const uint2 u3 = *(const uint2*)&g_support[(size_t)e3.x * F + lane * 4];
        fma_half4(acc, __int_as_float(e0.y), u0);
        fma_half4(acc, __int_as_float(e1.y), u1);
        fma_half4(acc, __int_as_float(e2.y), u2);
        fma_half4(acc, __int_as_float(e3.y), u3);
    }
    for (; base < e; base++) {
        const int2  ed = g_edge[base];
        const uint2 u  = *(const uint2*)&g_support[(size_t)ed.x * F + lane * 4];
        fma_half4(acc, __int_as_float(ed.y), u);
    }

    *(float4*)&out[(size_t)warp * F + lane * 4] = acc;
}

// ---------------------------------------------------------------------------
// Launch. Inputs: 0=x, 1=weight, 2=bias, 3=edge_vals, 4=edge_rows, 5=edge_cols
// ---------------------------------------------------------------------------
extern "C" void kernel_launch(void* const* d_in, const int* in_sizes, int n_in,
                              void* d_out, int out_size) {
    const float* x    = (const float*)d_in[0];
    const float* w    = (const float*)d_in[1];
    const float* bias = (const float*)d_in[2];
    const float* vals = (const float*)d_in[3];
    const int*   rows = (const int*)d_in[4];
    const int*   cols = (const int*)d_in[5];
    float*       out  = (float*)d_out;

    static bool attr_set = false;
    if (!attr_set) {
        cudaFuncSetAttribute(gemm_hist_kernel,
                             cudaFuncAttributeMaxDynamicSharedMemorySize, GEMM_SMEM);
        attr_set = true;
    }

    // 0) W^T -> fp16 (tiny)
    prep_w_kernel<<<(F * F + 255) / 256, 256>>>(w);
    // 1) GEMM (support = x @ W, fp16) + fused histogram + flag reset
    gemm_hist_kernel<<<GEMM_BLOCKS, GEMM_THREADS, GEMM_SMEM>>>(x, rows);
    // 2) single-pass scan -> g_start
    scan_fused_kernel<<<SCAN_BLOCKS, 1024>>>();
    // 3) MLP-4 scatter into CSR order (cursor decrements back to 0)
    scatter_kernel<<<(SCAT_NT + 255) / 256, 256>>>(rows, cols, vals);
    // 4) out = A_csr @ support + bias
    {
        const long long threads = (long long)N_NODES * 32;
        spmm_csr_kernel<<<(int)((threads + 255) / 256), 256>>>(bias, out);
    }
}

// round 17
// speedup vs baseline: 1.1157x; 1.1157x over previous
#include <cuda_runtime.h>
#include <cuda_fp16.h>
#include <cstdint>

#define N_NODES 50000
#define N_EDGES 625000
#define F 128
#define SCAN_BLOCKS 49          // 49 * 1024 = 50176 >= N_NODES
#define TILE_M 128
#define GEMM_BLOCKS ((N_NODES + TILE_M - 1) / TILE_M)   // 391
#define GEMM_THREADS 512
#define SPAD 136                // padded row stride (fp16 elems) -> conflict-free LDSM
#define TILE_BYTES (128 * SPAD * 2)                     // 34816
#define GEMM_SMEM (2 * TILE_BYTES)                      // A + B = 69632 -> 2 CTAs/SM
#define AGG_FLAG (1 << 30)

// ---------------------------------------------------------------------------
// Scratch (__device__ globals => allocation-free)
// Invariant: g_count[] == 0 at entry of every kernel_launch call
// (zero-init at load; spmm's per-row reset restores it each call).
// ---------------------------------------------------------------------------
__device__ __half g_support[(size_t)N_NODES * F]; // x @ W, fp16 (12.8 MB)
__device__ int    g_count[N_NODES];               // histogram -> scatter cursor
__device__ int    g_start[N_NODES + 1];           // CSR row starts
__device__ int2   g_edge[N_EDGES];                // packed {col, val} by row
__device__ int    g_agg[SCAN_BLOCKS];             // lookback aggregates
__device__ __half g_wt[F * F];                    // W^T (fp16), [n][k]

__device__ __forceinline__ uint32_t smem_u32(const void* p) {
    uint32_t a;
    asm("{ .reg .u64 t; cvta.to.shared.u64 t, %1; cvt.u32.u64 %0, t; }" : "=r"(a) : "l"(p));
    return a;
}

#define LDSM4(r0, r1, r2, r3, addr)                                              \
    asm volatile("ldmatrix.sync.aligned.m8n8.x4.shared.b16 {%0,%1,%2,%3}, [%4];" \
                 : "=r"(r0), "=r"(r1), "=r"(r2), "=r"(r3) : "r"(addr))

#define MMA16816F16(c, a0, a1, a2, a3, b0, b1)                                   \
    asm volatile("mma.sync.aligned.m16n8k16.row.col.f32.f16.f16.f32 "            \
                 "{%0,%1,%2,%3}, {%4,%5,%6,%7}, {%8,%9}, {%0,%1,%2,%3};"         \
                 : "+f"((c)[0]), "+f"((c)[1]), "+f"((c)[2]), "+f"((c)[3])        \
                 : "r"(a0), "r"(a1), "r"(a2), "r"(a3), "r"(b0), "r"(b1))

// ---------------------------------------------------------------------------
// Kernel A1: histogram of edge rows + lookback-flag reset   (side stream)
// ---------------------------------------------------------------------------
__global__ void hist_kernel(const int* __restrict__ rows) {
    const int gid = blockIdx.x * blockDim.x + threadIdx.x;
    if (gid < N_EDGES) atomicAdd(&g_count[rows[gid]], 1);
    if (gid < SCAN_BLOCKS) g_agg[gid] = 0;
}

// ---------------------------------------------------------------------------
// Kernel A2: single-pass exclusive scan of g_count -> g_start; also
// rewrites g_count[i] = start+count (scatter cursor = row END), so the
// scatter needs only ONE L2 op per edge (atomicSub), no g_start read.
// ---------------------------------------------------------------------------
__global__ __launch_bounds__(1024) void scan_fused_kernel() {
    __shared__ int wsum[32];
    __shared__ int blk_prev;
    const int t    = threadIdx.x;
    const int bid  = blockIdx.x;
    const int lane = t & 31;
    const int wid  = t >> 5;
    const int idx  = bid * 1024 + t;

    const int v = (idx < N_NODES) ? g_count[idx] : 0;

    int s = v;
    #pragma unroll
    for (int off = 1; off < 32; off <<= 1) {
        int n = __shfl_up_sync(0xffffffffu, s, off);
        if (lane >= off) s += n;
    }
    if (lane == 31) wsum[wid] = s;
    __syncthreads();

    if (wid == 0) {
        int ws = wsum[lane];
        #pragma unroll
        for (int off = 1; off < 32; off <<= 1) {
            int n = __shfl_up_sync(0xffffffffu, ws, off);
            if (lane >= off) ws += n;
        }
        wsum[lane] = ws;
        if (lane == 31) atomicExch(&g_agg[bid], ws | AGG_FLAG);

        int a = 0;
        for (int p = lane; p < bid; p += 32) {
            volatile int* agg = g_agg;
            int xv;
            do { xv = agg[p]; } while (!(xv & AGG_FLAG));
            a += xv & (AGG_FLAG - 1);
        }
        #pragma unroll
        for (int off = 16; off >= 1; off >>= 1)
            a += __shfl_xor_sync(0xffffffffu, a, off);
        if (lane == 0) blk_prev = a;
    }
    __syncthreads();

    const int wexcl = (wid > 0) ? wsum[wid - 1] : 0;
    if (idx < N_NODES) {
        const int start = blk_prev + wexcl + (s - v);
        g_start[idx] = start;
        g_count[idx] = start + v;              // cursor = row end
    }
    if (idx == 0) g_start[N_NODES] = N_EDGES;
}

// ---------------------------------------------------------------------------
// Kernel A3: scatter edges into CSR order — single atomic per edge.
// Cursor counts down from row end; spmm resets g_count to 0 afterwards.
// ---------------------------------------------------------------------------
__global__ void scatter_kernel(const int*   __restrict__ rows,
                               const int*   __restrict__ cols,
                               const float* __restrict__ vals) {
    int e = blockIdx.x * blockDim.x + threadIdx.x;
    if (e >= N_EDGES) return;
    int p = atomicSub(&g_count[rows[e]], 1) - 1;
    g_edge[p] = make_int2(cols[e], __float_as_int(vals[e]));
}

// ---------------------------------------------------------------------------
// Kernel B0: W^T fp16 convert (tiny)                       (capture stream)
// ---------------------------------------------------------------------------
__global__ void prep_w_kernel(const float* __restrict__ w) {
    int i = blockIdx.x * blockDim.x + threadIdx.x;   // i = n*F + k
    if (i >= F * F) return;
    int n = i >> 7, k = i & 127;
    g_wt[i] = __float2half(w[k * F + n]);
}

// ---------------------------------------------------------------------------
// Kernel B1: GEMM (single-term fp16 HMMA, 128x128 tile, 2 CTAs/SM)
// 512 threads; warp w: rows [16*(w>>1), +16), cols [64*(w&1), +64).
// ---------------------------------------------------------------------------
__global__ __launch_bounds__(GEMM_THREADS, 2)
void gemm_kernel(const float* __restrict__ x) {
    extern __shared__ char smem[];
    __half* sA = (__half*)smem;                  // 128 x SPAD fp16
    __half* sB = sA + 128 * SPAD;                // 128 x SPAD fp16 (W^T)

    const int t  = threadIdx.x;
    const int m0 = blockIdx.x * TILE_M;

    // ---- Load x tile, convert to fp16, padded stride ----
    #pragma unroll 4
    for (int i = 0; i < 8; i++) {
        int idx = t + GEMM_THREADS * i;          // 4096 float4 slots (128 x 32)
        int row = idx >> 5;
        int c4  = (idx & 31) * 4;
        int m   = m0 + row;
        float4 xv = (m < N_NODES) ? ((const float4*)x)[((size_t)m * F + c4) >> 2]
                                  : make_float4(0.f, 0.f, 0.f, 0.f);
        __half2 p0 = __floats2half2_rn(xv.x, xv.y);
        __half2 p1 = __floats2half2_rn(xv.z, xv.w);
        *(__half2*)&sA[row * SPAD + c4]     = p0;
        *(__half2*)&sA[row * SPAD + c4 + 2] = p1;
    }

    // ---- Copy pre-converted W^T (fp16) into smem, padded stride ----
    #pragma unroll
    for (int i = 0; i < 4; i++) {
        int idx = t + GEMM_THREADS * i;          // 2048 uint4 slots
        int n   = idx >> 4;
        int c8  = (idx & 15) * 8;
        *(uint4*)&sB[n * SPAD + c8] = *(const uint4*)&g_wt[n * F + c8];
    }
    __syncthreads();

    const int wid  = t >> 5;
    const int lane = t & 31;
    const int R    = (wid >> 1) * 16;            // row base (0..112)
    const int C0   = (wid & 1) * 64;             // col base

    float acc[8][4];
    #pragma unroll
    for (int i = 0; i < 8; i++)
        #pragma unroll
        for (int j = 0; j < 4; j++) acc[i][j] = 0.f;

    const uint32_t aBase = smem_u32(smem);
    const uint32_t bBase = aBase + TILE_BYTES;

    const int arow    = R + (lane & 7) + ((lane >> 3) & 1) * 8;
    const int acolh   = (lane >> 4) * 8;
    const int brow_in = (lane & 7) + ((lane >= 16) ? 8 : 0);
    const int bcolh   = ((lane >> 3) & 1) * 8;

    #pragma unroll 1
    for (int kc = 0; kc < 8; kc++) {
        const int k0 = kc * 16;
        uint32_t a0, a1, a2, a3;
        LDSM4(a0, a1, a2, a3, aBase + (uint32_t)((arow * SPAD + k0 + acolh) * 2));

        #pragma unroll
        for (int np = 0; np < 4; np++) {
            const int ncol = C0 + np * 16;
            uint32_t b0, b1, b2, b3;
            LDSM4(b0, b1, b2, b3,
                  bBase + (uint32_t)(((ncol + brow_in) * SPAD + k0 + bcolh) * 2));
            MMA16816F16(acc[2 * np],     a0, a1, a2, a3, b0, b1);
            MMA16816F16(acc[2 * np + 1], a0, a1, a2, a3, b2, b3);
        }
    }

    // ---- Epilogue: accum regs -> g_support as fp16 (half2 per 2 cols) ----
    const int g   = lane >> 2;
    const int tig = lane & 3;
    const int m1  = m0 + R + g;
    const int m2  = m1 + 8;
    #pragma unroll
    for (int nt = 0; nt < 8; nt++) {
        const int c = C0 + nt * 8 + tig * 2;
        if (m1 < N_NODES)
            *(__half2*)&g_support[(size_t)m1 * F + c] = __floats2half2_rn(acc[nt][0], acc[nt][1]);
        if (m2 < N_NODES)
            *(__half2*)&g_support[(size_t)m2 * F + c] = __floats2half2_rn(acc[nt][2], acc[nt][3]);
    }
}

// ---------------------------------------------------------------------------
// Kernel C: CSR SpMM: warp per row, 4-edge ILP, fp16 gathers (uint2/lane),
// fp32 accumulation, bias fused, atomic-free. Lane 0 resets g_count[row]=0
// (restores the all-zero invariant for the next call).
// ---------------------------------------------------------------------------
__device__ __forceinline__ void fma_half4(float4& acc, float v, uint2 u) {
    const float2 f0 = __half22float2(*reinterpret_cast<__half2*>(&u.x));
    const float2 f1 = __half22float2(*reinterpret_cast<__half2*>(&u.y));
    acc.x += v * f0.x; acc.y += v * f0.y;
    acc.z += v * f1.x; acc.w += v * f1.y;
}

__global__ __launch_bounds__(256) void spmm_csr_kernel(const float* __restrict__ bias,
                                                       float*       __restrict__ out) {
    const int warp = (blockIdx.x * blockDim.x + threadIdx.x) >> 5;
    const int lane = threadIdx.x & 31;
    if (warp >= N_NODES) return;

    if (lane == 0) g_count[warp] = 0;      // restore invariant

    const int s = g_start[warp];
    const int e = g_start[warp + 1];

    float4 acc = ((const float4*)bias)[lane];

    int base = s;
    for (; base + 4 <= e; base += 4) {
        const int2 e0 = g_edge[base + 0];
        const int2 e1 = g_edge[base + 1];
        const int2 e2 = g_edge[base + 2];
        const int2 e3 = g_edge[base + 3];
        const uint2 u0 = *(const uint2*)&g_support[(size_t)e0.x * F + lane * 4];
        const uint2 u1 = *(const uint2*)&g_support[(size_t)e1.x * F + lane * 4];
        const uint2 u2 = *(const uint2*)&g_support[(size_t)e2.x * F + lane * 4];
        const uint2 u3 = *(const uint2*)&g_support[(size_t)e3.x * F + lane * 4];
        fma_half4(acc, __int_as_float(e0.y), u0);
        fma_half4(acc, __int_as_float(e1.y), u1);
        fma_half4(acc, __int_as_float(e2.y), u2);
        fma_half4(acc, __int_as_float(e3.y), u3);
    }
    for (; base < e; base++) {
        const int2  ed = g_edge[base];
        const uint2 u  = *(const uint2*)&g_support[(size_t)ed.x * F + lane * 4];
        fma_half4(acc, __int_as_float(ed.y), u);
    }

    *(float4*)&out[(size_t)warp * F + lane * 4] = acc;
}

// ---------------------------------------------------------------------------
// Launch. Two parallel branches forked via events (graph-capture pattern):
//   branch A (side stream): hist -> scan -> scatter     (edge side)
//   branch B (main stream): prep_w -> gemm              (feature side)
// join -> spmm.
// Inputs: 0=x, 1=weight, 2=bias, 3=edge_vals, 4=edge_rows, 5=edge_cols
// ---------------------------------------------------------------------------
extern "C" void kernel_launch(void* const* d_in, const int* in_sizes, int n_in,
                              void* d_out, int out_size) {
    const float* x    = (const float*)d_in[0];
    const float* w    = (const float*)d_in[1];
    const float* bias = (const float*)d_in[2];
    const float* vals = (const float*)d_in[3];
    const int*   rows = (const int*)d_in[4];
    const int*   cols = (const int*)d_in[5];
    float*       out  = (float*)d_out;

    static cudaStream_t s2 = nullptr;
    static cudaEvent_t  evFork = nullptr, evJoin = nullptr;
    if (s2 == nullptr) {
        cudaStreamCreateWithFlags(&s2, cudaStreamNonBlocking);
        cudaEventCreateWithFlags(&evFork, cudaEventDisableTiming);
        cudaEventCreateWithFlags(&evJoin, cudaEventDisableTiming);
        cudaFuncSetAttribute(gemm_kernel,
                             cudaFuncAttributeMaxDynamicSharedMemorySize, GEMM_SMEM);
    }

    // fork
    cudaEventRecord(evFork, 0);
    cudaStreamWaitEvent(s2, evFork, 0);

    // branch A (side stream): CSR build
    hist_kernel<<<(N_EDGES + 255) / 256, 256, 0, s2>>>(rows);
    scan_fused_kernel<<<SCAN_BLOCKS, 1024, 0, s2>>>();
    scatter_kernel<<<(N_EDGES + 255) / 256, 256, 0, s2>>>(rows, cols, vals);
    cudaEventRecord(evJoin, s2);

    // branch B (main stream): support = x @ W (fp16)
    prep_w_kernel<<<(F * F + 255) / 256, 256>>>(w);
    gemm_kernel<<<GEMM_BLOCKS, GEMM_THREADS, GEMM_SMEM>>>(x);

    // join, then SpMM
    cudaStreamWaitEvent(0, evJoin, 0);
    {
        const long long threads = (long long)N_NODES * 32;
        spmm_csr_kernel<<<(int)((threads + 255) / 256), 256>>>(bias, out);
    }
}